// round 13
// baseline (speedup 1.0000x reference)
#include <cuda_runtime.h>
#include <cuda_fp16.h>
#include <cstdint>
#include <math.h>

#define D       256
#define NBANK   512
#define TMR     32          // rows (queries) per CTA
#define THREADS 256

// ---------------- device scratch (no allocation allowed) ----------------
__device__ __half g_embn_h[NBANK * D];   // l2-normalized bank fp16, [n][d] (K-major, GEMM1 B)
__device__ __half g_embT_h[D * NBANK];   // raw bank transposed fp16, [d][n] (K-major, GEMM2 B)

// ---------------- SMEM layout (bytes), two overlaid phases, 2 CTAs/SM ----------------
// ldmatrix row strides mod 128B: QH 528->16, B1 80->80(perm ok), EH 1040->16, B2 144->16
#define QH_LDH 264         // Q: 32 rows x 256 k (+8)
#define B1_LDH 40          // B1 chunk: 512 n-rows x 32 k (+8)
#define EH_LDH 520         // Eh: 32 rows x 512 k (+8)
#define B2_LDH 72          // B2 chunk: 256 d-rows x 64 k (+8)

#define OFF_QH   0                        // phase1: Q      [0     , 16896)
#define OFF_B1A  16896                    // phase1: B1 A   [16896 , 57856)
#define OFF_B1B  57856                    // phase1: B1 B   [57856 , 98816)
#define OFF_EH   0                        // phase2: Eh     [0     , 33280)
#define OFF_B2A  33280                    // phase2: B2 A   [33280 , 70144)
#define OFF_B2B  70144                    // phase2: B2 B   [70144 , 107008)
#define OFF_RINV 107008                   // 32 floats
#define OFF_PSUM 107136                   // 32 floats
#define SMEM_TOTAL 107264                 // 2 CTAs: 2*(107264+1024) = 216576 <= 233472

// ---------------- asm helpers (sm_80-era only; no 'a'-suffix features) ----------------
__device__ __forceinline__ uint32_t smem_u32(const void* p) {
    uint32_t a;
    asm("{ .reg .u64 t; cvta.to.shared.u64 t, %1; cvt.u32.u64 %0, t; }" : "=r"(a) : "l"(p));
    return a;
}
__device__ __forceinline__ void ldsm4(uint32_t* r, uint32_t a) {
    asm volatile("ldmatrix.sync.aligned.m8n8.x4.shared.b16 {%0,%1,%2,%3}, [%4];"
        : "=r"(r[0]), "=r"(r[1]), "=r"(r[2]), "=r"(r[3]) : "r"(a));
}
__device__ __forceinline__ void mma16816(float* c, const uint32_t* a, uint32_t b0, uint32_t b1) {
    asm volatile("mma.sync.aligned.m16n8k16.row.col.f32.f16.f16.f32 "
        "{%0,%1,%2,%3}, {%4,%5,%6,%7}, {%8,%9}, {%0,%1,%2,%3};"
        : "+f"(c[0]), "+f"(c[1]), "+f"(c[2]), "+f"(c[3])
        : "r"(a[0]), "r"(a[1]), "r"(a[2]), "r"(a[3]), "r"(b0), "r"(b1));
}
__device__ __forceinline__ void cpa16(uint32_t s, const void* g) {
    asm volatile("cp.async.cg.shared.global [%0], [%1], 16;" :: "r"(s), "l"(g));
}
__device__ __forceinline__ void cpa_commit() { asm volatile("cp.async.commit_group;" ::: "memory"); }
__device__ __forceinline__ void cpa_wait1()  { asm volatile("cp.async.wait_group 1;" ::: "memory"); }
__device__ __forceinline__ void cpa_wait0()  { asm volatile("cp.async.wait_group 0;" ::: "memory"); }

// exp(x), x in [-1.05, 1.05], FMA-only (avoids chip-wide MUFU floor for 134M exps)
__device__ __forceinline__ float fast_exp(float x) {
    float t = x * 1.4426950408889634f;
    float r = t + 12582912.0f;
    int   i = __float_as_int(r) - 0x4B400000;
    float f = t - (r - 12582912.0f);
    float p = 1.5403530393381608e-4f;
    p = fmaf(p, f, 1.3333558146428443e-3f);
    p = fmaf(p, f, 9.6181291076284770e-3f);
    p = fmaf(p, f, 5.5504108664821580e-2f);
    p = fmaf(p, f, 2.4022650695910071e-1f);
    p = fmaf(p, f, 6.9314718055994531e-1f);
    p = fmaf(p, f, 1.0f);
    return __int_as_float(__float_as_int(p) + (i << 23));
}

// ---------------- merged prologue: normalized bank + transposed raw bank ----------------
__global__ void prep_emb_kernel(const float* __restrict__ emb) {
    int n = blockIdx.x, t = threadIdx.x;     // 512 blocks x 256 threads
    float e = emb[n * D + t];
    __shared__ float red[8];
    float s = e * e;
    #pragma unroll
    for (int o = 16; o > 0; o >>= 1) s += __shfl_xor_sync(0xffffffffu, s, o);
    if ((t & 31) == 0) red[t >> 5] = s;
    __syncthreads();
    if (t < 8) {
        float v = red[t];
        #pragma unroll
        for (int o = 4; o > 0; o >>= 1) v += __shfl_xor_sync(0x000000ffu, v, o);
        if (t == 0) red[0] = v;
    }
    __syncthreads();
    float inv = 1.0f / fmaxf(sqrtf(red[0]), 1e-12f);
    g_embn_h[n * D + t] = __float2half(e * inv);
    g_embT_h[(size_t)t * NBANK + n] = __float2half(e);
}

// ---------------- cp.async chunk loaders (256 threads, one commit group each) ----------------
// B1 chunk: n512 x k32 (GEMM1 B), k-offset kc*32
__device__ __forceinline__ void load_b1_chunk(uint32_t sb, int bufoff, int kc, int tid) {
    const __half* gp = g_embn_h + kc * 32;
    #pragma unroll
    for (int i = 0; i < 8; i++) {                       // 512 rows x 4 segs of 16B
        int idx = i * 256 + tid;
        int row = idx >> 2, seg = idx & 3;
        cpa16(sb + bufoff + row * (B1_LDH * 2) + seg * 16, gp + (size_t)row * D + seg * 8);
    }
    cpa_commit();
}
// B2 chunk: d256 x k64 (GEMM2 B), k-offset kc*64
__device__ __forceinline__ void load_b2_chunk(uint32_t sb, int bufoff, int kc, int tid) {
    const __half* gp = g_embT_h + kc * 64;
    #pragma unroll
    for (int i = 0; i < 8; i++) {                       // 256 rows x 8 segs of 16B
        int idx = i * 256 + tid;
        int row = idx >> 3, seg = idx & 7;
        cpa16(sb + bufoff + row * (B2_LDH * 2) + seg * 16, gp + (size_t)row * NBANK + seg * 8);
    }
    cpa_commit();
}

// ---------------- main fused kernel: 8 warps, 1m x 8n warp grid, 2 CTAs/SM ----------------
__global__ __launch_bounds__(THREADS, 2)
void concept_mma_kernel(const float* __restrict__ q,
                        float* __restrict__ vec_out,
                        float* __restrict__ p_out) {
    extern __shared__ char smem[];
    const uint32_t sb = smem_u32(smem);
    const int tid  = threadIdx.x;
    const int lane = tid & 31;
    const int wn   = tid >> 5;                   // 8 warps, 1m x 8n (m32 x n64 / d32 tiles)
    const size_t b0 = (size_t)blockIdx.x * TMR;

    float* rinvs = (float*)(smem + OFF_RINV);
    float* psum  = (float*)(smem + OFF_PSUM);
    if (tid < TMR) psum[tid] = 0.f;

    // preload GEMM1 k-chunks 0,1 (overlaps Q conversion)
    load_b1_chunk(sb, OFF_B1A, 0, tid);
    load_b1_chunk(sb, OFF_B1B, 1, tid);

    // ---- Q: load f32 (8 threads/row), ssq via shuffle, fp16 to SMEM ----
    {
        const int qrow = tid >> 3, qq = tid & 7;     // 32 rows, 32 floats/thread
        const float* qr = q + (b0 + qrow) * D + qq * 32;
        float ss = 0.f;
        #pragma unroll
        for (int i = 0; i < 8; i++) {
            float4 v = *(const float4*)(qr + i * 4);
            ss = fmaf(v.x, v.x, ss); ss = fmaf(v.y, v.y, ss);
            ss = fmaf(v.z, v.z, ss); ss = fmaf(v.w, v.w, ss);
            __half2 h0 = __floats2half2_rn(v.x, v.y);
            __half2 h1 = __floats2half2_rn(v.z, v.w);
            uint2 u = make_uint2(*(uint32_t*)&h0, *(uint32_t*)&h1);
            *(uint2*)(smem + OFF_QH + (qrow * QH_LDH + qq * 32 + i * 4) * 2) = u;
        }
        ss += __shfl_xor_sync(0xffffffffu, ss, 1);
        ss += __shfl_xor_sync(0xffffffffu, ss, 2);
        ss += __shfl_xor_sync(0xffffffffu, ss, 4);
        if ((lane & 7) == 0) rinvs[qrow] = 1.0f / fmaxf(sqrtf(ss), 1e-12f);
    }

    // ldmatrix lane->address maps (proven R9-R11)
    const int g    = lane >> 3;
    const int arow = (g & 1) * 8 + (lane & 7);
    const int ak   = (g >> 1) * 8;
    const int brow = (g >> 1) * 8 + (lane & 7);
    const int bk   = (g & 1) * 8;

    // ---- Phase 1: GEMM1  sims[32x512] = Qh @ embn^T  (warp m32 x n64; 8 k32-chunks) ----
    float acc[2][8][4];
    #pragma unroll
    for (int mt = 0; mt < 2; mt++)
        #pragma unroll
        for (int nt = 0; nt < 8; nt++)
            #pragma unroll
            for (int k = 0; k < 4; k++) acc[mt][nt][k] = 0.f;

    #pragma unroll 1
    for (int kc = 0; kc < 8; kc++) {
        if (kc < 7) cpa_wait1(); else cpa_wait0();
        __syncthreads();                               // also publishes Q on kc==0
        const uint32_t buf   = sb + ((kc & 1) ? OFF_B1B : OFF_B1A);
        const uint32_t abase = sb + OFF_QH + ((arow)*QH_LDH + kc * 32 + ak) * 2;
        const uint32_t bbase = buf + ((wn * 64 + brow) * B1_LDH + bk) * 2;

        #pragma unroll
        for (int ks = 0; ks < 2; ks++) {
            const uint32_t ko = (uint32_t)ks * 32;
            uint32_t af[8], bf[16];
            ldsm4(af,      abase + ko);
            ldsm4(af + 4,  abase + 16 * QH_LDH * 2 + ko);
            ldsm4(bf,      bbase + ko);
            ldsm4(bf + 4,  bbase + 16 * B1_LDH * 2 + ko);
            ldsm4(bf + 8,  bbase + 32 * B1_LDH * 2 + ko);
            ldsm4(bf + 12, bbase + 48 * B1_LDH * 2 + ko);
            #pragma unroll
            for (int mt = 0; mt < 2; mt++)
                #pragma unroll
                for (int nt = 0; nt < 8; nt++)
                    mma16816(acc[mt][nt], af + mt * 4, bf[nt * 2], bf[nt * 2 + 1]);
        }
        __syncthreads();                               // buffer free before refill
        if (kc + 2 < 8) load_b1_chunk(sb, (kc & 1) ? OFF_B1B : OFF_B1A, kc + 2, tid);
    }

    // ---- epilogue: exp in-place in acc, row sums, Eh store (B1/QH dead after last sync) ----
    float rv[2][2];
    #pragma unroll
    for (int mt = 0; mt < 2; mt++)
        #pragma unroll
        for (int h = 0; h < 2; h++)
            rv[mt][h] = rinvs[mt * 16 + (lane >> 2) + h * 8];

    float rs[2][2] = {{0.f, 0.f}, {0.f, 0.f}};
    #pragma unroll
    for (int mt = 0; mt < 2; mt++)
        #pragma unroll
        for (int nt = 0; nt < 8; nt++)
            #pragma unroll
            for (int h = 0; h < 2; h++) {
                float e0 = fast_exp(acc[mt][nt][2 * h]     * rv[mt][h]);
                float e1 = fast_exp(acc[mt][nt][2 * h + 1] * rv[mt][h]);
                rs[mt][h] += e0 + e1;
                acc[mt][nt][2 * h] = e0; acc[mt][nt][2 * h + 1] = e1;
            }
    #pragma unroll
    for (int mt = 0; mt < 2; mt++)
        #pragma unroll
        for (int h = 0; h < 2; h++) {
            float v = rs[mt][h];
            v += __shfl_xor_sync(0xffffffffu, v, 1);
            v += __shfl_xor_sync(0xffffffffu, v, 2);
            if ((lane & 3) == 0)
                atomicAdd(&psum[mt * 16 + (lane >> 2) + h * 8], v);
        }
    // Eh (fp16) for GEMM2 A operand
    #pragma unroll
    for (int mt = 0; mt < 2; mt++)
        #pragma unroll
        for (int h = 0; h < 2; h++) {
            const int r = mt * 16 + (lane >> 2) + h * 8;
            #pragma unroll
            for (int nt = 0; nt < 8; nt++) {
                __half2 hh = __floats2half2_rn(acc[mt][nt][2 * h], acc[mt][nt][2 * h + 1]);
                const int col = wn * 64 + nt * 8 + (lane & 3) * 2;
                *(uint32_t*)(smem + OFF_EH + (r * EH_LDH + col) * 2) = *(uint32_t*)&hh;
            }
        }
    __syncthreads();                                   // Eh + psum complete

    load_b2_chunk(sb, OFF_B2A, 0, tid);                // overlaps pinv + p stores
    if (tid < TMR) psum[tid] = 1.0f / psum[tid];
    __syncthreads();

    // ---- p output directly from registers: p = e * pinv (float2, 32B sectors) ----
    #pragma unroll
    for (int mt = 0; mt < 2; mt++)
        #pragma unroll
        for (int h = 0; h < 2; h++) {
            const int r = mt * 16 + (lane >> 2) + h * 8;
            const float pv = psum[r];
            #pragma unroll
            for (int nt = 0; nt < 8; nt++) {
                const int col = wn * 64 + nt * 8 + (lane & 3) * 2;
                *(float2*)(p_out + (b0 + r) * NBANK + col) =
                    make_float2(acc[mt][nt][2 * h] * pv, acc[mt][nt][2 * h + 1] * pv);
            }
        }
    load_b2_chunk(sb, OFF_B2B, 1, tid);

    // ---- Phase 2: GEMM2  vec[32x256] = Eh @ embT^T  (warp m32 x d32; 8 k64-chunks) ----
    float ac2[2][4][4];
    #pragma unroll
    for (int mt = 0; mt < 2; mt++)
        #pragma unroll
        for (int nt = 0; nt < 4; nt++)
            #pragma unroll
            for (int k = 0; k < 4; k++) ac2[mt][nt][k] = 0.f;

    #pragma unroll 1
    for (int kc = 0; kc < 8; kc++) {
        if (kc < 7) cpa_wait1(); else cpa_wait0();
        __syncthreads();
        const uint32_t buf   = sb + ((kc & 1) ? OFF_B2B : OFF_B2A);
        const uint32_t abase = sb + OFF_EH + ((arow)*EH_LDH + kc * 64 + ak) * 2;
        const uint32_t bbase = buf + ((wn * 32 + brow) * B2_LDH + bk) * 2;

        #pragma unroll
        for (int ks = 0; ks < 4; ks++) {
            const uint32_t ko = (uint32_t)ks * 32;
            uint32_t af[8], bf[8];
            ldsm4(af,     abase + ko);
            ldsm4(af + 4, abase + 16 * EH_LDH * 2 + ko);
            ldsm4(bf,     bbase + ko);
            ldsm4(bf + 4, bbase + 16 * B2_LDH * 2 + ko);
            #pragma unroll
            for (int mt = 0; mt < 2; mt++)
                #pragma unroll
                for (int nt = 0; nt < 4; nt++)
                    mma16816(ac2[mt][nt], af + mt * 4, bf[nt * 2], bf[nt * 2 + 1]);
        }
        __syncthreads();
        if (kc + 2 < 8) load_b2_chunk(sb, (kc & 1) ? OFF_B2B : OFF_B2A, kc + 2, tid);
    }

    // ---- vec epilogue: vec = acc2 * pinv ----
    #pragma unroll
    for (int mt = 0; mt < 2; mt++)
        #pragma unroll
        for (int h = 0; h < 2; h++) {
            const int r = mt * 16 + (lane >> 2) + h * 8;
            const float pv = psum[r];
            #pragma unroll
            for (int nt = 0; nt < 4; nt++) {
                const int d = wn * 32 + nt * 8 + (lane & 3) * 2;
                *(float2*)(vec_out + (b0 + r) * D + d) =
                    make_float2(ac2[mt][nt][2 * h] * pv, ac2[mt][nt][2 * h + 1] * pv);
            }
        }
}

extern "C" void kernel_launch(void* const* d_in, const int* in_sizes, int n_in,
                              void* d_out, int out_size) {
    const float* q   = (const float*)d_in[0];   // (B, 256)
    const float* emb = (const float*)d_in[1];   // (512, 256)
    const int B = in_sizes[0] / D;

    float* vec_out = (float*)d_out;                     // (B, 256)
    float* p_out   = (float*)d_out + (size_t)B * D;     // (B, 512)

    cudaFuncSetAttribute(concept_mma_kernel,
                         cudaFuncAttributeMaxDynamicSharedMemorySize, SMEM_TOTAL);

    prep_emb_kernel<<<NBANK, D>>>(emb);
    concept_mma_kernel<<<B / TMR, THREADS, SMEM_TOTAL>>>(q, vec_out, p_out);
}

// round 15
// speedup vs baseline: 1.2914x; 1.2914x over previous
#include <cuda_runtime.h>
#include <cuda_fp16.h>
#include <cstdint>
#include <math.h>

#define D       256
#define NBANK   512
#define TMR     64
#define THREADS 256
#define BTOT    262144

// ---------------- device scratch (static __device__, no allocation) ----------------
__device__ __half g_embn_h[NBANK * D];     // l2-normalized bank fp16 [n][d]
__device__ __half g_embT_h[D * NBANK];     // raw bank transposed fp16 [d][n]
__device__ __half g_Ph[(size_t)BTOT * NBANK];  // unnormalized exp(sims) fp16 [b][n] (256MB)
__device__ float  g_rsum[BTOT];            // per-row sum of exps

// ---------------- K1 SMEM ----------------
#define QH_LDH 264          // Q: 64 x 256 (+8)
#define B1_LDH 72           // B1 chunk: 256 n-rows x 64 k (+8)
#define K1_OFF_QH   0
#define K1_OFF_B1A  33792
#define K1_OFF_B1B  70656
#define K1_OFF_RINV 107520
#define K1_OFF_PSUM (K1_OFF_RINV + 256)
#define K1_SMEM     (K1_OFF_PSUM + 256)    // 108032 -> 2 CTAs/SM

// ---------------- K2 SMEM ----------------
#define A2_LDH 72           // A chunk: 64 rows x 64 k (+8)
#define B2_LDH 72           // B chunk: 256 d-rows x 64 k (+8)
#define K2_OFF_AA   0
#define K2_OFF_AB   9216
#define K2_OFF_BA   18432
#define K2_OFF_BB   55296
#define K2_OFF_PINV 92160
#define K2_SMEM     (K2_OFF_PINV + 256)    // 92416 -> 2 CTAs/SM

// ---------------- asm helpers (sm_80-era only) ----------------
__device__ __forceinline__ uint32_t smem_u32(const void* p) {
    uint32_t a;
    asm("{ .reg .u64 t; cvta.to.shared.u64 t, %1; cvt.u32.u64 %0, t; }" : "=r"(a) : "l"(p));
    return a;
}
__device__ __forceinline__ void ldsm4(uint32_t* r, uint32_t a) {
    asm volatile("ldmatrix.sync.aligned.m8n8.x4.shared.b16 {%0,%1,%2,%3}, [%4];"
        : "=r"(r[0]), "=r"(r[1]), "=r"(r[2]), "=r"(r[3]) : "r"(a));
}
__device__ __forceinline__ void mma16816(float* c, const uint32_t* a, uint32_t b0, uint32_t b1) {
    asm volatile("mma.sync.aligned.m16n8k16.row.col.f32.f16.f16.f32 "
        "{%0,%1,%2,%3}, {%4,%5,%6,%7}, {%8,%9}, {%0,%1,%2,%3};"
        : "+f"(c[0]), "+f"(c[1]), "+f"(c[2]), "+f"(c[3])
        : "r"(a[0]), "r"(a[1]), "r"(a[2]), "r"(a[3]), "r"(b0), "r"(b1));
}
__device__ __forceinline__ void cpa16(uint32_t s, const void* g) {
    asm volatile("cp.async.cg.shared.global [%0], [%1], 16;" :: "r"(s), "l"(g));
}
__device__ __forceinline__ void cpa_commit() { asm volatile("cp.async.commit_group;" ::: "memory"); }
__device__ __forceinline__ void cpa_wait1()  { asm volatile("cp.async.wait_group 1;" ::: "memory"); }
__device__ __forceinline__ void cpa_wait0()  { asm volatile("cp.async.wait_group 0;" ::: "memory"); }

// exp(x), x in [-1.05, 1.05], FMA-only
__device__ __forceinline__ float fast_exp(float x) {
    float t = x * 1.4426950408889634f;
    float r = t + 12582912.0f;
    int   i = __float_as_int(r) - 0x4B400000;
    float f = t - (r - 12582912.0f);
    float p = 1.5403530393381608e-4f;
    p = fmaf(p, f, 1.3333558146428443e-3f);
    p = fmaf(p, f, 9.6181291076284770e-3f);
    p = fmaf(p, f, 5.5504108664821580e-2f);
    p = fmaf(p, f, 2.4022650695910071e-1f);
    p = fmaf(p, f, 6.9314718055994531e-1f);
    p = fmaf(p, f, 1.0f);
    return __int_as_float(__float_as_int(p) + (i << 23));
}

// ---------------- prologue ----------------
__global__ void prep_emb_kernel(const float* __restrict__ emb) {
    int n = blockIdx.x, t = threadIdx.x;
    float e = emb[n * D + t];
    __shared__ float red[8];
    float s = e * e;
    #pragma unroll
    for (int o = 16; o > 0; o >>= 1) s += __shfl_xor_sync(0xffffffffu, s, o);
    if ((t & 31) == 0) red[t >> 5] = s;
    __syncthreads();
    if (t < 8) {
        float v = red[t];
        #pragma unroll
        for (int o = 4; o > 0; o >>= 1) v += __shfl_xor_sync(0x000000ffu, v, o);
        if (t == 0) red[0] = v;
    }
    __syncthreads();
    float inv = 1.0f / fmaxf(sqrtf(red[0]), 1e-12f);
    g_embn_h[n * D + t] = __float2half(e * inv);
    g_embT_h[(size_t)t * NBANK + n] = __float2half(e);
}

// ---------------- K1: e = exp(sims), row sums ----------------
// B1 chunk: n256 x k64 at (nc, kc) -> 256 rows x 8 segs of 16B = 2048 cpa16
__device__ __forceinline__ void k1_load_b1(uint32_t sb, int bufoff, int nc, int kc, int tid) {
    const __half* gp = g_embn_h + (size_t)nc * 256 * D + kc * 64;
    #pragma unroll
    for (int i = 0; i < 8; i++) {
        int idx = i * 256 + tid;
        int row = idx >> 3, seg = idx & 7;
        cpa16(sb + bufoff + row * (B1_LDH * 2) + seg * 16, gp + (size_t)row * D + seg * 8);
    }
    cpa_commit();
}

__global__ __launch_bounds__(THREADS, 2)
void k1_gemm_exp(const float* __restrict__ q) {
    extern __shared__ char smem[];
    const uint32_t sb = smem_u32(smem);
    const int tid = threadIdx.x, lane = tid & 31, w = tid >> 5;
    const int wm = w >> 2, wn = w & 3;             // 2m x 4n, warp m32 x n64
    const size_t b0 = (size_t)blockIdx.x * TMR;

    float* rinvs = (float*)(smem + K1_OFF_RINV);
    float* psum  = (float*)(smem + K1_OFF_PSUM);
    if (tid < TMR) psum[tid] = 0.f;

    k1_load_b1(sb, K1_OFF_B1A, 0, 0, tid);
    k1_load_b1(sb, K1_OFF_B1B, 0, 1, tid);

    // Q load (4 threads/row), ssq, fp16 to smem
    {
        const int qrow = tid >> 2, qq = tid & 3;
        const float* qr = q + (b0 + qrow) * D + qq * 64;
        float ss = 0.f;
        #pragma unroll
        for (int i = 0; i < 16; i++) {
            float4 v = *(const float4*)(qr + i * 4);
            ss = fmaf(v.x, v.x, ss); ss = fmaf(v.y, v.y, ss);
            ss = fmaf(v.z, v.z, ss); ss = fmaf(v.w, v.w, ss);
            __half2 h0 = __floats2half2_rn(v.x, v.y);
            __half2 h1 = __floats2half2_rn(v.z, v.w);
            uint2 u = make_uint2(*(uint32_t*)&h0, *(uint32_t*)&h1);
            *(uint2*)(smem + K1_OFF_QH + (qrow * QH_LDH + qq * 64 + i * 4) * 2) = u;
        }
        ss += __shfl_xor_sync(0xffffffffu, ss, 1);
        ss += __shfl_xor_sync(0xffffffffu, ss, 2);
        if ((lane & 3) == 0) rinvs[qrow] = 1.0f / fmaxf(sqrtf(ss), 1e-12f);
    }

    const int g    = lane >> 3;
    const int arow = (g & 1) * 8 + (lane & 7);
    const int ak   = (g >> 1) * 8;
    const int brow = (g >> 1) * 8 + (lane & 7);
    const int bk   = (g & 1) * 8;

    float rv[2][2];
    bool rv_ok = false;
    float acc[2][8][4];
    float rs[2][2] = {{0.f, 0.f}, {0.f, 0.f}};

    #pragma unroll 1
    for (int c = 0; c < 8; c++) {                  // nc = c>>2 (2 halves), kc = c&3 (k64)
        const int nc = c >> 2, kc = c & 3;
        if (c < 7) cpa_wait1(); else cpa_wait0();
        __syncthreads();                           // publishes Q on c==0

        if (kc == 0) {
            #pragma unroll
            for (int mt = 0; mt < 2; mt++)
                #pragma unroll
                for (int nt = 0; nt < 8; nt++)
                    #pragma unroll
                    for (int k = 0; k < 4; k++) acc[mt][nt][k] = 0.f;
        }
        const uint32_t abase = sb + K1_OFF_QH + ((wm * 32 + arow) * QH_LDH + kc * 64 + ak) * 2;
        const uint32_t bbase = sb + ((c & 1) ? K1_OFF_B1B : K1_OFF_B1A)
                             + ((wn * 64 + brow) * B1_LDH + bk) * 2;
        #pragma unroll
        for (int ks = 0; ks < 4; ks++) {
            const uint32_t ko = (uint32_t)ks * 32;
            uint32_t af[8], bf[16];
            ldsm4(af,      abase + ko);
            ldsm4(af + 4,  abase + 16 * QH_LDH * 2 + ko);
            ldsm4(bf,      bbase + ko);
            ldsm4(bf + 4,  bbase + 16 * B1_LDH * 2 + ko);
            ldsm4(bf + 8,  bbase + 32 * B1_LDH * 2 + ko);
            ldsm4(bf + 12, bbase + 48 * B1_LDH * 2 + ko);
            #pragma unroll
            for (int mt = 0; mt < 2; mt++)
                #pragma unroll
                for (int nt = 0; nt < 8; nt++)
                    mma16816(acc[mt][nt], af + mt * 4, bf[nt * 2], bf[nt * 2 + 1]);
        }
        __syncthreads();
        if (c + 2 < 8) k1_load_b1(sb, (c & 1) ? K1_OFF_B1B : K1_OFF_B1A,
                                  (c + 2) >> 2, (c + 2) & 3, tid);

        if (kc == 3) {                             // epilogue for this n256-half
            if (!rv_ok) {
                #pragma unroll
                for (int mt = 0; mt < 2; mt++)
                    #pragma unroll
                    for (int h = 0; h < 2; h++)
                        rv[mt][h] = rinvs[wm * 32 + mt * 16 + (lane >> 2) + h * 8];
                rv_ok = true;
            }
            #pragma unroll
            for (int mt = 0; mt < 2; mt++)
                #pragma unroll
                for (int h = 0; h < 2; h++) {
                    const int r = wm * 32 + mt * 16 + (lane >> 2) + h * 8;
                    __half* prow = g_Ph + (b0 + r) * NBANK + nc * 256 + wn * 64;
                    #pragma unroll
                    for (int nt = 0; nt < 8; nt++) {
                        float e0 = fast_exp(acc[mt][nt][2 * h]     * rv[mt][h]);
                        float e1 = fast_exp(acc[mt][nt][2 * h + 1] * rv[mt][h]);
                        rs[mt][h] += e0 + e1;
                        __half2 hh = __floats2half2_rn(e0, e1);
                        *(uint32_t*)(prow + nt * 8 + (lane & 3) * 2) = *(uint32_t*)&hh;
                    }
                }
        }
    }

    // row sums -> global
    #pragma unroll
    for (int mt = 0; mt < 2; mt++)
        #pragma unroll
        for (int h = 0; h < 2; h++) {
            float v = rs[mt][h];
            v += __shfl_xor_sync(0xffffffffu, v, 1);
            v += __shfl_xor_sync(0xffffffffu, v, 2);
            if ((lane & 3) == 0)
                atomicAdd(&psum[wm * 32 + mt * 16 + (lane >> 2) + h * 8], v);
        }
    __syncthreads();
    if (tid < TMR) g_rsum[b0 + tid] = psum[tid];
}

// ---------------- K2: vec = (e @ embT^T)*pinv, p = e*pinv ----------------
// A chunk: 64 rows x 8 segs of 16B = 512 cpa16
__device__ __forceinline__ void k2_load_a(uint32_t sb, int bufoff, size_t b0, int kc, int tid) {
    const __half* gp = g_Ph + b0 * NBANK + kc * 64;
    #pragma unroll
    for (int i = 0; i < 2; i++) {
        int idx = i * 256 + tid;
        int row = idx >> 3, seg = idx & 7;
        cpa16(sb + bufoff + row * (A2_LDH * 2) + seg * 16, gp + (size_t)row * NBANK + seg * 8);
    }
}
// B chunk: 256 rows x 8 segs of 16B = 2048 cpa16
__device__ __forceinline__ void k2_load_b(uint32_t sb, int bufoff, int kc, int tid) {
    const __half* gp = g_embT_h + kc * 64;
    #pragma unroll
    for (int i = 0; i < 8; i++) {
        int idx = i * 256 + tid;
        int row = idx >> 3, seg = idx & 7;
        cpa16(sb + bufoff + row * (B2_LDH * 2) + seg * 16, gp + (size_t)row * NBANK + seg * 8);
    }
    cpa_commit();                                  // one group = A+B of a chunk
}

__global__ __launch_bounds__(THREADS, 2)
void k2_gemm_out(float* __restrict__ vec_out, float* __restrict__ p_out) {
    extern __shared__ char smem[];
    const uint32_t sb = smem_u32(smem);
    const int tid = threadIdx.x, lane = tid & 31, wn = tid >> 5;   // 1m x 8n, warp m64 x d32
    const size_t b0 = (size_t)blockIdx.x * TMR;

    float* pinv = (float*)(smem + K2_OFF_PINV);
    if (tid < TMR) pinv[tid] = 1.0f / g_rsum[b0 + tid];

    k2_load_a(sb, K2_OFF_AA, b0, 0, tid);
    k2_load_b(sb, K2_OFF_BA, 0, tid);
    k2_load_a(sb, K2_OFF_AB, b0, 1, tid);
    k2_load_b(sb, K2_OFF_BB, 1, tid);

    const int g    = lane >> 3;
    const int arow = (g & 1) * 8 + (lane & 7);
    const int ak   = (g >> 1) * 8;
    const int brow = (g >> 1) * 8 + (lane & 7);
    const int bk   = (g & 1) * 8;

    float acc[4][4][4];
    #pragma unroll
    for (int mt = 0; mt < 4; mt++)
        #pragma unroll
        for (int nt = 0; nt < 4; nt++)
            #pragma unroll
            for (int k = 0; k < 4; k++) acc[mt][nt][k] = 0.f;

    #pragma unroll 1
    for (int kc = 0; kc < 8; kc++) {
        if (kc < 7) cpa_wait1(); else cpa_wait0();
        __syncthreads();
        const uint32_t abuf = sb + ((kc & 1) ? K2_OFF_AB : K2_OFF_AA);
        const uint32_t bbuf = sb + ((kc & 1) ? K2_OFF_BB : K2_OFF_BA);

        // p epilogue from the freshly-arrived A tile: p = e * pinv (float4, coalesced)
        #pragma unroll
        for (int i = 0; i < 4; i++) {
            int idx = i * 256 + tid;
            int row = idx >> 4, cs = (idx & 15) * 4;
            uint2 u = *(uint2*)(smem + (abuf - sb) + (row * A2_LDH + cs) * 2);
            __half2 h0 = *(__half2*)&u.x, h1 = *(__half2*)&u.y;
            float2 f0 = __half22float2(h0), f1 = __half22float2(h1);
            float pv = pinv[row];
            *(float4*)(p_out + (b0 + row) * NBANK + kc * 64 + cs) =
                make_float4(f0.x * pv, f0.y * pv, f1.x * pv, f1.y * pv);
        }

        const uint32_t abase = abuf + ((arow)*A2_LDH + ak) * 2;
        const uint32_t bbase = bbuf + ((wn * 32 + brow) * B2_LDH + bk) * 2;
        #pragma unroll
        for (int ks = 0; ks < 4; ks++) {
            const uint32_t ko = (uint32_t)ks * 32;
            uint32_t af[16], bf[8];
            ldsm4(af,      abase + ko);
            ldsm4(af + 4,  abase + 16 * A2_LDH * 2 + ko);
            ldsm4(af + 8,  abase + 32 * A2_LDH * 2 + ko);
            ldsm4(af + 12, abase + 48 * A2_LDH * 2 + ko);
            ldsm4(bf,      bbase + ko);
            ldsm4(bf + 4,  bbase + 16 * B2_LDH * 2 + ko);
            #pragma unroll
            for (int mt = 0; mt < 4; mt++)
                #pragma unroll
                for (int nt = 0; nt < 4; nt++)
                    mma16816(acc[mt][nt], af + mt * 4, bf[nt * 2], bf[nt * 2 + 1]);
        }
        __syncthreads();
        if (kc + 2 < 8) {
            k2_load_a(sb, (kc & 1) ? K2_OFF_AB : K2_OFF_AA, b0, kc + 2, tid);
            k2_load_b(sb, (kc & 1) ? K2_OFF_BB : K2_OFF_BA, kc + 2, tid);
        }
    }

    // vec epilogue
    #pragma unroll
    for (int mt = 0; mt < 4; mt++)
        #pragma unroll
        for (int h = 0; h < 2; h++) {
            const int r = mt * 16 + (lane >> 2) + h * 8;
            const float pv = pinv[r];
            #pragma unroll
            for (int nt = 0; nt < 4; nt++) {
                const int d = wn * 32 + nt * 8 + (lane & 3) * 2;
                *(float2*)(vec_out + (b0 + r) * D + d) =
                    make_float2(acc[mt][nt][2 * h] * pv, acc[mt][nt][2 * h + 1] * pv);
            }
        }
}

extern "C" void kernel_launch(void* const* d_in, const int* in_sizes, int n_in,
                              void* d_out, int out_size) {
    const float* q   = (const float*)d_in[0];   // (B, 256)
    const float* emb = (const float*)d_in[1];   // (512, 256)
    const int B = in_sizes[0] / D;

    float* vec_out = (float*)d_out;                     // (B, 256)
    float* p_out   = (float*)d_out + (size_t)B * D;     // (B, 512)

    cudaFuncSetAttribute(k1_gemm_exp,
                         cudaFuncAttributeMaxDynamicSharedMemorySize, K1_SMEM);
    cudaFuncSetAttribute(k2_gemm_out,
                         cudaFuncAttributeMaxDynamicSharedMemorySize, K2_SMEM);

    prep_emb_kernel<<<NBANK, D>>>(emb);
    k1_gemm_exp<<<B / TMR, THREADS, K1_SMEM>>>(q);
    k2_gemm_out<<<B / TMR, THREADS, K2_SMEM>>>(vec_out, p_out);
}